// round 7
// baseline (speedup 1.0000x reference)
#include <cuda_runtime.h>
#include <cuda_fp16.h>
#include <math.h>
#include <stdint.h>

#define NN 207
#define BB 32
#define TT 12
#define CC 2
#define HORZ 12
#define DID 64
#define HH 128
#define CONCATN 2560          // DID + TT + NN*TT
#define MROWS (BB*NN*CC)      // 13248
#define MPAD 13440            // 140*96
#define BNCNT (BB*NN)         // 6624
#define EPSILON_V 10.0f
#define EPS_V 1e-8f

// ---------------- scratch (device globals; no allocation) ----------------
__device__ __half g_Xh[(size_t)MPAD * CONCATN]; // ~68MB fp16
__device__ __half g_H0[MPAD * HH];
__device__ __half g_H1[MPAD * HH];
__device__ float g_F[MPAD * HORZ];
__device__ float g_hin[BNCNT * TT * CC];
__device__ float g_level[BNCNT * CC];
__device__ float g_tgf[BNCNT * HORZ];
__device__ float g_dp[NN * NN];
// transposed weights (N x K, K-major), fp16
__device__ __half g_W0t[3 * HH * CONCATN];
__device__ __half g_Wfct[3 * 2 * HH * HH];
__device__ __half g_Wbt[3 * CONCATN * HH];

// ---------------- helpers ----------------
__device__ __forceinline__ uint32_t smem_u32(const void* p) {
    uint32_t a;
    asm("{ .reg .u64 t; cvta.to.shared.u64 t, %1; cvt.u32.u64 %0, t; }" : "=r"(a) : "l"(p));
    return a;
}
#define CP_ASYNC16(s, g) asm volatile("cp.async.cg.shared.global [%0], [%1], 16;" :: "r"(s), "l"(g))
#define CP_COMMIT()      asm volatile("cp.async.commit_group;" ::: "memory")
#define CP_WAIT(n)       asm volatile("cp.async.wait_group %0;" :: "n"(n) : "memory")

__device__ __forceinline__ void mma_f16(float* d, const uint32_t* a, const uint32_t* b) {
    asm volatile("mma.sync.aligned.m16n8k16.row.col.f32.f16.f16.f32 "
                 "{%0,%1,%2,%3}, {%4,%5,%6,%7}, {%8,%9}, {%0,%1,%2,%3};"
                 : "+f"(d[0]), "+f"(d[1]), "+f"(d[2]), "+f"(d[3])
                 : "r"(a[0]), "r"(a[1]), "r"(a[2]), "r"(a[3]), "r"(b[0]), "r"(b[1]));
}
__device__ __forceinline__ __half2 h2_from(float a, float b) {
    return __floats2half2_rn(a, b);
}

// ---------------- time gates + h_in + level ----------------
__global__ void timegate_kernel(const float* __restrict__ hist,
                                const float* __restrict__ tod,
                                const float* __restrict__ emb,
                                const float* __restrict__ w1, const float* __restrict__ b1,
                                const float* __restrict__ w2, const float* __restrict__ b2,
                                const float* __restrict__ w3, const float* __restrict__ b3) {
    int bn = blockIdx.x;
    int n = bn % NN;
    __shared__ float sin_[DID + TT];
    __shared__ float stg[HH];
    __shared__ float stgb[TT];
    __shared__ float shin[TT * CC];
    int t = threadIdx.x;  // 128
    if (t < DID) sin_[t] = emb[n * DID + t];
    else if (t < DID + TT) sin_[t] = tod[bn * TT + (t - DID)];
    __syncthreads();
    float acc = b1[t];
#pragma unroll 4
    for (int i = 0; i < DID + TT; i++) acc += sin_[i] * w1[i * HH + t];
    stg[t] = fmaxf(acc, 0.f);
    __syncthreads();
    if (t < HORZ) {
        float a2 = b2[t], a3 = b3[t];
#pragma unroll 8
        for (int h = 0; h < HH; h++) {
            float v = stg[h];
            a2 += v * w2[h * HORZ + t];
            a3 += v * w3[h * TT + t];
        }
        g_tgf[bn * HORZ + t] = a2;
        stgb[t] = a3;
    }
    __syncthreads();
    if (t < TT * CC) {
        int tt = t >> 1, c = t & 1;
        float hv = hist[((size_t)bn * TT + tt) * CC + c] / (1.f + stgb[tt]);
        shin[t] = hv;
        g_hin[bn * TT * CC + t] = hv;
    }
    __syncthreads();
    if (t < CC) {
        float mx = -1e30f;
#pragma unroll
        for (int tt = 0; tt < TT; tt++) mx = fmaxf(mx, shin[tt * CC + t]);
        g_level[bn * CC + t] = mx;
    }
}

// ---------------- pairwise affinities ----------------
__global__ void dp_kernel(const float* __restrict__ emb) {
    int idx = blockIdx.x * blockDim.x + threadIdx.x;
    if (idx >= NN * NN) return;
    int i = idx / NN, j = idx % NN;
    float s = 0.f;
#pragma unroll 8
    for (int k = 0; k < DID; k++) s += emb[i * DID + k] * emb[j * DID + k];
    g_dp[idx] = expf(EPSILON_V * s);
}

// ---------------- zero the M-pad rows of X ----------------
__global__ void pad_zero_kernel() {
    int idx = blockIdx.x * blockDim.x + threadIdx.x;
    int total = (MPAD - MROWS) * CONCATN / 2;
    if (idx < total)
        reinterpret_cast<uint32_t*>(&g_Xh[(size_t)MROWS * CONCATN])[idx] = 0u;
}

// ---------------- build X (fp16 output) ----------------
__global__ void build_hist_kernel(const float* __restrict__ emb) {
    int bn = blockIdx.x;
    int b = bn / NN, n = bn % NN;
    __shared__ float sh[NN * TT * CC];
    __shared__ float sdp[NN];
    __shared__ float slvl[CC];
    int tid = threadIdx.x;               // 256
    for (int i = tid; i < NN * TT * CC; i += 256) sh[i] = g_hin[b * NN * TT * CC + i];
    for (int i = tid; i < NN; i += 256) sdp[i] = g_dp[n * NN + i];
    if (tid < CC) slvl[tid] = g_level[bn * CC + tid];
    __syncthreads();
    float lv[2] = {slvl[0], slvl[1]};
    float rl[2] = {1.f / (lv[0] + EPS_V), 1.f / (lv[1] + EPS_V)};
    __half* xb = &g_Xh[(size_t)bn * CC * CONCATN];

    for (int pair = tid; pair < 2 * NN; pair += 256) {
        int c = (pair >= NN) ? 1 : 0;
        int src = pair - NN * c;
        float d = sdp[src];
        float l = lv[c], r = rl[c];
        float v[12];
#pragma unroll
        for (int t = 0; t < 12; t++) {
            float a = sh[(src * 12 + t) * 2 + c] * d;
            v[t] = fmaxf((a - l) * r, 0.f);
        }
        __half2* dst = reinterpret_cast<__half2*>(xb + (size_t)c * CONCATN + 12 + src * 12);
#pragma unroll
        for (int q = 0; q < 6; q++) dst[q] = h2_from(v[2 * q], v[2 * q + 1]);
    }
    if (tid < 24) {
        int c = tid >= 12 ? 1 : 0;
        int t = tid - 12 * c;
        xb[(size_t)c * CONCATN + t] = __float2half_rn(sh[(n * 12 + t) * 2 + c] * rl[c]);
    }
    if (tid < 128) {
        int c = tid >> 6, d = tid & 63;
        xb[(size_t)c * CONCATN + (TT + NN * TT) + d] = __float2half_rn(emb[n * DID + d]);
    }
}

// ---------------- batched weight transpose -> fp16 (N x K) ----------------
__global__ void transpose_all_kernel(const float* __restrict__ fc0_w,
                                     const float* __restrict__ fc_w,
                                     const float* __restrict__ back_w) {
    __shared__ float t[32][33];
    int idx = blockIdx.x;
    int blk = idx / 672;
    int r = idx % 672;
    const float* in;
    __half* out;
    int K, N, kb, nb;
    if (r < 320) {
        in = fc0_w + (size_t)blk * CONCATN * HH;
        out = g_W0t + (size_t)blk * HH * CONCATN;
        K = CONCATN; N = HH; kb = (r % 80) * 32; nb = (r / 80) * 32;
    } else if (r < 336) {
        r -= 320;
        in = fc_w + ((size_t)blk * 2 + 0) * HH * HH;
        out = g_Wfct + ((size_t)blk * 2 + 0) * HH * HH;
        K = HH; N = HH; kb = (r % 4) * 32; nb = (r / 4) * 32;
    } else if (r < 352) {
        r -= 336;
        in = fc_w + ((size_t)blk * 2 + 1) * HH * HH;
        out = g_Wfct + ((size_t)blk * 2 + 1) * HH * HH;
        K = HH; N = HH; kb = (r % 4) * 32; nb = (r / 4) * 32;
    } else {
        r -= 352;
        in = back_w + (size_t)blk * HH * CONCATN;
        out = g_Wbt + (size_t)blk * CONCATN * HH;
        K = HH; N = CONCATN; kb = (r % 4) * 32; nb = (r / 4) * 32;
    }
    int x = threadIdx.x, y = threadIdx.y;  // 32 x 8
#pragma unroll
    for (int rr = 0; rr < 32; rr += 8)
        t[y + rr][x] = in[(size_t)(kb + y + rr) * N + nb + x];
    __syncthreads();
#pragma unroll
    for (int rr = 0; rr < 32; rr += 8)
        out[(size_t)(nb + y + rr) * K + kb + x] = __float2half_rn(t[x][y + rr]);
}

// ---------------- fp16 mma.sync GEMM (fp16 A, fp16 weights, fp32 accum) ----------------
// C(96 x 128 tile) = A(MxK) @ Wt(NxK)^T, 3-stage cp.async.
// 256 threads = 8 warps (2x4), warp tile 48x32.
// EPI 0: Ch = relu(acc + bias) fp16
// EPI 1: Ch = relu(Ch - (acc + bias)) in-place fp16
// EPI 3: fused backcast: Cf(=d_out, interleaved fp32) = relu(Xold - v), row < MROWS
#define G_BM 96
#define G_BN 128
#define SA_STR 40                        // halves per A smem row
#define SB_STR 40                        // halves per B smem row
#define A_STG_B (G_BM * SA_STR * 2)      // 7680 bytes
#define B_STG_B (G_BN * SB_STR * 2)      // 10240 bytes
#define STG_B (A_STG_B + B_STG_B)        // 17920 bytes
#define G_SMEM (3 * STG_B)               // 53760 bytes

template <int EPI>
__global__ void __launch_bounds__(256) gemm_mma_kernel(
        const __half* __restrict__ A, const __half* __restrict__ Bt,
        const float* __restrict__ bias, __half* __restrict__ Ch,
        float* __restrict__ Cf, const __half* __restrict__ Xold,
        int Nout, int K) {
    extern __shared__ char smc[];
    const int tid = threadIdx.x;
    const int wid = tid >> 5, lid = tid & 31;
    const int wm = wid >> 2, wn = wid & 3;
    const int g = lid >> 2, t = lid & 3;
    const int m0 = blockIdx.x * G_BM, n0 = blockIdx.y * G_BN;

    const __half* gA = A + (size_t)m0 * K;
    const __half* gB = Bt + (size_t)n0 * K;
    const uint32_t sm_u = smem_u32(smc);

    auto load_tiles = [&](int k0, int st) {
        uint32_t base = sm_u + st * STG_B;
        // A: 96 rows x 32 halves = 384 16B chunks
#pragma unroll
        for (int p = 0; p < 2; p++) {
            int idx = tid + (p << 8);
            if (idx < 384) {
                int row = idx >> 2, kh = (idx & 3) << 3;
                CP_ASYNC16(base + (row * SA_STR + kh) * 2, gA + (size_t)row * K + k0 + kh);
            }
        }
        uint32_t baseB = base + A_STG_B;
        // B: 128 rows x 32 halves = 512 chunks
#pragma unroll
        for (int p = 0; p < 2; p++) {
            int idx = tid + (p << 8);
            int row = idx >> 2, kh = (idx & 3) << 3;
            CP_ASYNC16(baseB + (row * SB_STR + kh) * 2, gB + (size_t)row * K + k0 + kh);
        }
        CP_COMMIT();
    };

    float acc[3][4][4];
#pragma unroll
    for (int mf = 0; mf < 3; mf++)
#pragma unroll
        for (int nf = 0; nf < 4; nf++)
#pragma unroll
            for (int q = 0; q < 4; q++) acc[mf][nf][q] = 0.f;

    const int nch = K >> 5;
    load_tiles(0, 0);
    if (nch > 1) load_tiles(32, 1);

    for (int ch = 0; ch < nch; ch++) {
        int st = ch % 3;
        if (ch + 2 < nch) {
            load_tiles((ch + 2) << 5, (ch + 2) % 3);
            CP_WAIT(2);
        } else if (ch + 1 < nch) {
            CP_WAIT(1);
        } else {
            CP_WAIT(0);
        }
        __syncthreads();

        const uint32_t* sA = reinterpret_cast<const uint32_t*>(smc + st * STG_B);
        const uint32_t* sB = reinterpret_cast<const uint32_t*>(smc + st * STG_B + A_STG_B);
#pragma unroll
        for (int ks = 0; ks < 2; ks++) {
            uint32_t af[3][4];
#pragma unroll
            for (int mf = 0; mf < 3; mf++) {
                int r = wm * 48 + mf * 16 + g;
                int base = r * (SA_STR / 2) + ks * 8 + t;
                af[mf][0] = sA[base];
                af[mf][1] = sA[base + 8 * (SA_STR / 2)];
                af[mf][2] = sA[base + 4];
                af[mf][3] = sA[base + 8 * (SA_STR / 2) + 4];
            }
            uint32_t bf[4][2];
#pragma unroll
            for (int nf = 0; nf < 4; nf++) {
                int n = wn * 32 + nf * 8 + g;
                int base = n * (SB_STR / 2) + ks * 8 + t;
                bf[nf][0] = sB[base];
                bf[nf][1] = sB[base + 4];
            }
#pragma unroll
            for (int mf = 0; mf < 3; mf++)
#pragma unroll
                for (int nf = 0; nf < 4; nf++)
                    mma_f16(acc[mf][nf], af[mf], bf[nf]);
        }
        __syncthreads();
    }

    // epilogue
#pragma unroll
    for (int mf = 0; mf < 3; mf++) {
#pragma unroll
        for (int nf = 0; nf < 4; nf++) {
            int row = m0 + wm * 48 + mf * 16 + g;
            int col = n0 + wn * 32 + nf * 8 + 2 * t;
            float2 bv = *reinterpret_cast<const float2*>(&bias[col]);
            float v0 = acc[mf][nf][0] + bv.x;
            float v1 = acc[mf][nf][1] + bv.y;
            float v2 = acc[mf][nf][2] + bv.x;
            float v3 = acc[mf][nf][3] + bv.y;
            if (EPI == 0) {
                *reinterpret_cast<__half2*>(&Ch[(size_t)row * Nout + col]) =
                    h2_from(fmaxf(v0, 0.f), fmaxf(v1, 0.f));
                *reinterpret_cast<__half2*>(&Ch[(size_t)(row + 8) * Nout + col]) =
                    h2_from(fmaxf(v2, 0.f), fmaxf(v3, 0.f));
            } else if (EPI == 1) {
                __half2* p0 = reinterpret_cast<__half2*>(&Ch[(size_t)row * Nout + col]);
                __half2* p1 = reinterpret_cast<__half2*>(&Ch[(size_t)(row + 8) * Nout + col]);
                float2 o0 = __half22float2(*p0);
                float2 o1 = __half22float2(*p1);
                *p0 = h2_from(fmaxf(o0.x - v0, 0.f), fmaxf(o0.y - v1, 0.f));
                *p1 = h2_from(fmaxf(o1.x - v2, 0.f), fmaxf(o1.y - v3, 0.f));
            } else {
                if (row < MROWS) {
                    float2 o0 = __half22float2(
                        *reinterpret_cast<const __half2*>(&Xold[(size_t)row * Nout + col]));
                    size_t ob = (size_t)(row >> 1) * (2 * CONCATN) + (size_t)col * 2 + (row & 1);
                    Cf[ob] = fmaxf(o0.x - v0, 0.f);
                    Cf[ob + 2] = fmaxf(o0.y - v1, 0.f);
                }
                int row2 = row + 8;
                if (row2 < MROWS) {
                    float2 o1 = __half22float2(
                        *reinterpret_cast<const __half2*>(&Xold[(size_t)row2 * Nout + col]));
                    size_t ob = (size_t)(row2 >> 1) * (2 * CONCATN) + (size_t)col * 2 + (row2 & 1);
                    Cf[ob] = fmaxf(o1.x - v2, 0.f);
                    Cf[ob + 2] = fmaxf(o1.y - v3, 0.f);
                }
            }
        }
    }
}

// ---------------- small GEMM for forecast head (fp16 A, Nout=12) ----------------
#define BM 64
#define BN 64
#define BKK 16

template <int EPI>   // 2 = store, 3 = accumulate
__global__ void sgemm_kernel(const __half* __restrict__ A, const float* __restrict__ Bw,
                             const float* __restrict__ bias, float* __restrict__ Cout,
                             int M, int Nout, int K) {
    __shared__ float As[BKK][BM + 4];
    __shared__ float Bs[BKK][BN];
    int m0 = blockIdx.x * BM;
    int n0 = blockIdx.y * BN;
    int tid = threadIdx.x;
    int tx = tid & 15, ty = tid >> 4;
    float acc[4][4] = {};
    int arow = tid >> 2;
    int ac4 = (tid & 3) * 4;
    int bk = tid >> 4;
    int bn4 = (tid & 15) * 4;
    for (int k0 = 0; k0 < K; k0 += BKK) {
        const __half* ap = A + (size_t)(m0 + arow) * K + k0 + ac4;
        float2 a01 = __half22float2(*reinterpret_cast<const __half2*>(ap));
        float2 a23 = __half22float2(*reinterpret_cast<const __half2*>(ap + 2));
        As[ac4 + 0][arow] = a01.x;
        As[ac4 + 1][arow] = a01.y;
        As[ac4 + 2][arow] = a23.x;
        As[ac4 + 3][arow] = a23.y;
#pragma unroll
        for (int j = 0; j < 4; j++) {
            int nc = n0 + bn4 + j;
            Bs[bk][bn4 + j] = (nc < Nout) ? Bw[(size_t)(k0 + bk) * Nout + nc] : 0.f;
        }
        __syncthreads();
#pragma unroll
        for (int k = 0; k < BKK; k++) {
            float4 a4 = *reinterpret_cast<const float4*>(&As[k][ty * 4]);
            float4 b4 = *reinterpret_cast<const float4*>(&Bs[k][tx * 4]);
            float a[4] = {a4.x, a4.y, a4.z, a4.w};
            float b[4] = {b4.x, b4.y, b4.z, b4.w};
#pragma unroll
            for (int i = 0; i < 4; i++)
#pragma unroll
                for (int j = 0; j < 4; j++) acc[i][j] += a[i] * b[j];
        }
        __syncthreads();
    }
#pragma unroll
    for (int i = 0; i < 4; i++) {
        int row = m0 + ty * 4 + i;
#pragma unroll
        for (int j = 0; j < 4; j++) {
            int col = n0 + tx * 4 + j;
            if (col < Nout) {
                float v = acc[i][j] + bias[col];
                size_t off = (size_t)row * Nout + col;
                if (EPI == 2) Cout[off] = v;
                else Cout[off] += v;
            }
        }
    }
}

// ---------------- forecast output ----------------
__global__ void forecast_out_kernel(float* __restrict__ out) {
    int idx = blockIdx.x * blockDim.x + threadIdx.x;
    if (idx >= BNCNT * HORZ * CC) return;
    int c = idx & 1;
    int h = (idx >> 1) % HORZ;
    int bn = idx / (HORZ * CC);
    float v = g_F[((size_t)bn * CC + c) * HORZ + h];
    v *= g_level[bn * CC + c];
    v *= (1.f + g_tgf[bn * HORZ + h]);
    out[idx] = v;
}

// ---------------- launcher ----------------
extern "C" void kernel_launch(void* const* d_in, const int* in_sizes, int n_in,
                              void* d_out, int out_size) {
    const float* history = (const float*)d_in[0];
    const float* tod     = (const float*)d_in[1];
    const float* emb     = (const float*)d_in[2];
    const float* tg1_w = (const float*)d_in[3];
    const float* tg1_b = (const float*)d_in[4];
    const float* tg2_w = (const float*)d_in[5];
    const float* tg2_b = (const float*)d_in[6];
    const float* tg3_w = (const float*)d_in[7];
    const float* tg3_b = (const float*)d_in[8];
    const float* fc0_w = (const float*)d_in[9];
    const float* fc0_b = (const float*)d_in[10];
    const float* fc_w  = (const float*)d_in[11];
    const float* fc_b  = (const float*)d_in[12];
    const float* fore_w = (const float*)d_in[13];
    const float* fore_b = (const float*)d_in[14];
    const float* back_w = (const float*)d_in[15];
    const float* back_b = (const float*)d_in[16];
    float* out = (float*)d_out;

    float *pF;
    __half *pX, *pH0, *pH1, *pW0t, *pWfct, *pWbt;
    cudaGetSymbolAddress((void**)&pX, g_Xh);
    cudaGetSymbolAddress((void**)&pH0, g_H0);
    cudaGetSymbolAddress((void**)&pH1, g_H1);
    cudaGetSymbolAddress((void**)&pF, g_F);
    cudaGetSymbolAddress((void**)&pW0t, g_W0t);
    cudaGetSymbolAddress((void**)&pWfct, g_Wfct);
    cudaGetSymbolAddress((void**)&pWbt, g_Wbt);

    cudaFuncSetAttribute(gemm_mma_kernel<0>, cudaFuncAttributeMaxDynamicSharedMemorySize, G_SMEM);
    cudaFuncSetAttribute(gemm_mma_kernel<1>, cudaFuncAttributeMaxDynamicSharedMemorySize, G_SMEM);
    cudaFuncSetAttribute(gemm_mma_kernel<3>, cudaFuncAttributeMaxDynamicSharedMemorySize, G_SMEM);

    timegate_kernel<<<BNCNT, 128>>>(history, tod, emb, tg1_w, tg1_b, tg2_w, tg2_b, tg3_w, tg3_b);
    dp_kernel<<<(NN * NN + 255) / 256, 256>>>(emb);
    pad_zero_kernel<<<((MPAD - MROWS) * CONCATN / 2 + 255) / 256, 256>>>();
    transpose_all_kernel<<<2016, dim3(32, 8)>>>(fc0_w, fc_w, back_w);
    build_hist_kernel<<<BNCNT, 256>>>(emb);

    const int GMX = MPAD / G_BM;   // 140
    for (int i = 0; i < 3; i++) {
        gemm_mma_kernel<0><<<dim3(GMX, 1), 256, G_SMEM>>>(
            pX, pW0t + (size_t)i * HH * CONCATN, fc0_b + i * HH, pH0, nullptr, nullptr, HH, CONCATN);
        gemm_mma_kernel<0><<<dim3(GMX, 1), 256, G_SMEM>>>(
            pH0, pWfct + ((size_t)i * 2 + 0) * HH * HH, fc_b + (i * 2 + 0) * HH, pH1, nullptr, nullptr, HH, HH);
        gemm_mma_kernel<0><<<dim3(GMX, 1), 256, G_SMEM>>>(
            pH1, pWfct + ((size_t)i * 2 + 1) * HH * HH, fc_b + (i * 2 + 1) * HH, pH0, nullptr, nullptr, HH, HH);
        if (i == 0)
            sgemm_kernel<2><<<dim3(MPAD / BM, 1), 256>>>(
                pH0, fore_w + (size_t)i * HH * HORZ, fore_b + i * HORZ, pF, MPAD, HORZ, HH);
        else
            sgemm_kernel<3><<<dim3(MPAD / BM, 1), 256>>>(
                pH0, fore_w + (size_t)i * HH * HORZ, fore_b + i * HORZ, pF, MPAD, HORZ, HH);
        if (i < 2)
            gemm_mma_kernel<1><<<dim3(GMX, CONCATN / G_BN), 256, G_SMEM>>>(
                pH0, pWbt + (size_t)i * CONCATN * HH, back_b + (size_t)i * CONCATN, pX, nullptr, nullptr, CONCATN, HH);
        else
            gemm_mma_kernel<3><<<dim3(GMX, CONCATN / G_BN), 256, G_SMEM>>>(
                pH0, pWbt + (size_t)i * CONCATN * HH, back_b + (size_t)i * CONCATN, nullptr, out, pX, CONCATN, HH);
    }

    forecast_out_kernel<<<(BNCNT * HORZ * CC + 255) / 256, 256>>>(out + (size_t)MROWS * CONCATN);
}